// round 3
// baseline (speedup 1.0000x reference)
#include <cuda_runtime.h>
#include <cstdint>

// Problem constants
#define N_PIX   131072      // 32 * 64 * 64 pixels (B*H*W)
#define K_CODES 512
#define D_DIM   64

// Output layout (float32 concat in reference return order):
// [0]                      quant_loss (1)
// [1 .. 8388609)           quantized_out [32,64,64,64]  (8388608)
// [8388609]                perplexity (1)
// [8388610 .. 75497474)    encodings [131072, 512]      (67108864)
// [75497474 .. 75628546)   idx [131072, 1]              (131072)
#define OFF_LOSS 0ULL
#define OFF_Q    1ULL
#define OFF_PERP 8388609ULL
#define OFF_ENC  8388610ULL
#define OFF_IDX  75497474ULL

__device__ double g_sumsq;
__device__ int    g_counts[K_CODES];
__device__ float  g_sume[K_CODES];

// ---------- packed f32x2 helpers (sm_103a FFMA2 via PTX only) ----------
__device__ __forceinline__ unsigned long long fma2(unsigned long long a,
                                                   unsigned long long b,
                                                   unsigned long long c) {
    unsigned long long d;
    asm("fma.rn.f32x2 %0, %1, %2, %3;" : "=l"(d) : "l"(a), "l"(b), "l"(c));
    return d;
}
__device__ __forceinline__ unsigned long long pack2(float lo, float hi) {
    unsigned long long d;
    asm("mov.b64 %0, {%1, %2};" : "=l"(d) : "f"(lo), "f"(hi));
    return d;
}
__device__ __forceinline__ void unpack2(unsigned long long v, float& lo, float& hi) {
    asm("mov.b64 {%0, %1}, %2;" : "=f"(lo), "=f"(hi) : "l"(v));
}

// ---------- prep: zero scratch, compute ||e_k||^2 ----------
__global__ void vq_prep(const float* __restrict__ emb) {
    int k = threadIdx.x;            // 512 threads
    if (k == 0) g_sumsq = 0.0;
    const float* row = emb + k * D_DIM;
    float s = 0.f;
#pragma unroll
    for (int c = 0; c < D_DIM; c++)
        s = __fadd_rn(s, __fmul_rn(row[c], row[c]));
    g_sume[k] = s;
    g_counts[k] = 0;
}

// ---------- main kernel ----------
extern __shared__ float4 smem_raw4[];

__global__ __launch_bounds__(256) void vq_main(const float* __restrict__ z,
                                               const float* __restrict__ emb,
                                               float* __restrict__ out) {
    // dynamic smem layout:
    // [0, 131072)           codebook (512x64 f32)
    // [131072, 133120)      sume (512 f32)
    // [133120, 134144)      per-thread chosen idx (256 i32)
    char*  smem_raw = (char*)smem_raw4;
    float* s_emb = (float*)smem_raw;
    float* s_se  = (float*)(smem_raw + 131072);
    int*   s_idx = (int*)  (smem_raw + 133120);
    __shared__ double s_red[256];

    const int tid = threadIdx.x;

    // cooperative stage of codebook into smem (32768 floats = 8192 float4)
    {
        const float4* e4 = (const float4*)emb;
        float4* s4 = (float4*)s_emb;
#pragma unroll 8
        for (int i = tid; i < 8192; i += 256) s4[i] = e4[i];
        for (int i = tid; i < K_CODES; i += 256) s_se[i] = g_sume[i];
    }
    __syncthreads();

    const int n = blockIdx.x * 256 + tid;       // pixel id, N_PIX = 512*256 exactly
    const int w = n & 63;
    const int h = (n >> 6) & 63;
    const int b = n >> 12;
    const size_t zbase = (size_t)b * 262144 + (size_t)h * 64 + (size_t)w;
    const float* zg = z + zbase;

    // load z (strided by H*W=4096 over channel) and compute ||z||^2 sequentially
    unsigned long long zp[32];
    float sumz = 0.f;
#pragma unroll
    for (int i = 0; i < 32; i++) {
        float a = zg[(2 * i) * 4096];
        float c = zg[(2 * i + 1) * 4096];
        sumz = __fadd_rn(sumz, __fmul_rn(a, a));
        sumz = __fadd_rn(sumz, __fmul_rn(c, c));
        zp[i] = pack2(a, c);
    }

    // argmin over 512 codes: dist = (sumz + sume_k) - 2*dot   (match ref op order)
    float best = 3.4e38f;
    int bidx = 0;
    const ulonglong2* s2 = (const ulonglong2*)s_emb;
#pragma unroll 2
    for (int k = 0; k < K_CODES; k++) {
        const ulonglong2* row = s2 + k * 16;
        unsigned long long acc0 = 0ULL, acc1 = 0ULL;   // packed {0.f,0.f}
#pragma unroll
        for (int i = 0; i < 16; i++) {
            ulonglong2 ev = row[i];                    // 4 consecutive e floats
            acc0 = fma2(zp[2 * i],     ev.x, acc0);
            acc1 = fma2(zp[2 * i + 1], ev.y, acc1);
        }
        float a0, a1, a2, a3;
        unpack2(acc0, a0, a1);
        unpack2(acc1, a2, a3);
        float dot  = __fadd_rn(__fadd_rn(a0, a1), __fadd_rn(a2, a3));
        float t1   = __fadd_rn(sumz, s_se[k]);
        float dist = __fsub_rn(t1, __fmul_rn(2.0f, dot));
        if (dist < best) { best = dist; bidx = k; }    // strict <: first index on tie
    }

    s_idx[tid] = bidx;

    // quantized_st = fl(z + fl(q - z))  (NOT bitwise q), accumulate (q - z)^2
    float lsum = 0.f;
    float* qout = out + OFF_Q + zbase;
    const float* erow = s_emb + bidx * D_DIM;
#pragma unroll
    for (int i = 0; i < 32; i++) {
        float zlo, zhi;
        unpack2(zp[i], zlo, zhi);
        float q0 = erow[2 * i];
        float q1 = erow[2 * i + 1];
        float d0 = __fsub_rn(q0, zlo);
        float d1 = __fsub_rn(q1, zhi);
        lsum += d0 * d0 + d1 * d1;
        qout[(2 * i) * 4096]     = __fadd_rn(zlo, d0);
        qout[(2 * i + 1) * 4096] = __fadd_rn(zhi, d1);
    }

    out[OFF_IDX + (size_t)n] = (float)bidx;
    atomicAdd(&g_counts[bidx], 1);

    // block-reduce squared error (double), one atomic per block
    s_red[tid] = (double)lsum;
    __syncthreads();                 // also publishes s_idx
#pragma unroll
    for (int off = 128; off > 0; off >>= 1) {
        if (tid < off) s_red[tid] += s_red[tid + off];
        __syncthreads();
    }
    if (tid == 0) atomicAdd(&g_sumsq, s_red[0]);

    // cooperative coalesced one-hot write: each warp writes 32 rows of 512 floats.
    // OFF_ENC is only 8-byte aligned (8388610 % 4 == 2) -> use float2 stores.
    const int lane = tid & 31;
    const int warp = tid >> 5;
    const size_t enc_base = OFF_ENC + (size_t)(blockIdx.x * 256) * K_CODES;
    for (int r = warp * 32; r < warp * 32 + 32; r++) {
        const int target = s_idx[r];
        float2* rowp = (float2*)(out + enc_base + (size_t)r * K_CODES);
#pragma unroll
        for (int j = lane; j < 256; j += 32) {
            int c0 = j * 2;
            float2 v;
            v.x = (c0     == target) ? 1.f : 0.f;
            v.y = (c0 + 1 == target) ? 1.f : 0.f;
            rowp[j] = v;
        }
    }
}

// ---------- finalize: loss + perplexity ----------
__global__ void vq_final(float* __restrict__ out) {
    __shared__ double sh[K_CODES];
    int k = threadIdx.x;            // 512 threads
    // mean_enc = count / 131072 is exact in fp32 (power-of-two divide)
    float pf = (float)g_counts[k] * (1.0f / 131072.0f);
    float term = pf * logf(pf + 1e-10f);   // p=0 -> 0 * log(1e-10) = 0, like ref
    sh[k] = (double)term;
    __syncthreads();
#pragma unroll
    for (int off = 256; off > 0; off >>= 1) {
        if (k < off) sh[k] += sh[k + off];
        __syncthreads();
    }
    if (k == 0) {
        out[OFF_PERP] = expf((float)(-sh[0]));
        double m = g_sumsq / 8388608.0;            // mean over B*H*W*D
        float mf = (float)m;
        // ref: loss = m + 0.25*m with both terms identical values
        out[OFF_LOSS] = __fadd_rn(mf, __fmul_rn(0.25f, mf));
    }
}

extern "C" void kernel_launch(void* const* d_in, const int* in_sizes, int n_in,
                              void* d_out, int out_size) {
    const float* z   = (const float*)d_in[0];   // latent_z [32,64,64,64]
    const float* emb = (const float*)d_in[1];   // embedding [512,64]
    float* out = (float*)d_out;

    vq_prep<<<1, 512>>>(emb);

    const int dyn_smem = 134144;  // 128KB codebook + 2KB norms + 1KB idx
    cudaFuncSetAttribute(vq_main, cudaFuncAttributeMaxDynamicSharedMemorySize, dyn_smem);
    vq_main<<<N_PIX / 256, 256, dyn_smem>>>(z, emb, out);

    vq_final<<<1, 512>>>(out);
}

// round 4
// speedup vs baseline: 1.2912x; 1.2912x over previous
#include <cuda_runtime.h>
#include <cstdint>

// Problem constants
#define N_PIX   131072      // 32 * 64 * 64 pixels (B*H*W)
#define K_CODES 512
#define D_DIM   64
#define TPB     256
#define PPT     2                       // pixels per thread
#define PIX_PER_BLK (TPB * PPT)         // 512
#define NBLK    (N_PIX / PIX_PER_BLK)   // 256

// Output layout (float32 concat in reference return order):
#define OFF_LOSS 0ULL
#define OFF_Q    1ULL
#define OFF_PERP 8388609ULL
#define OFF_ENC  8388610ULL
#define OFF_IDX  75497474ULL

// zeroed each call via one cudaMemsetAsync (graph-capturable memset node)
struct Scratch {
    int    counts[K_CODES];
    double sumsq;
    int    ticket;
};
__device__ Scratch g_s;

// ---------- packed f32x2 helpers (sm_103a FFMA2 via PTX only) ----------
__device__ __forceinline__ unsigned long long fma2(unsigned long long a,
                                                   unsigned long long b,
                                                   unsigned long long c) {
    unsigned long long d;
    asm("fma.rn.f32x2 %0, %1, %2, %3;" : "=l"(d) : "l"(a), "l"(b), "l"(c));
    return d;
}
__device__ __forceinline__ unsigned long long pack2(float lo, float hi) {
    unsigned long long d;
    asm("mov.b64 %0, {%1, %2};" : "=l"(d) : "f"(lo), "f"(hi));
    return d;
}
__device__ __forceinline__ void unpack2(unsigned long long v, float& lo, float& hi) {
    asm("mov.b64 {%0, %1}, %2;" : "=f"(lo), "=f"(hi) : "l"(v));
}

extern __shared__ float4 smem_raw4[];

__global__ __launch_bounds__(TPB, 1) void vq_fused(const float* __restrict__ z,
                                                   const float* __restrict__ emb,
                                                   float* __restrict__ out) {
    // dynamic smem: [0,131072) codebook | [131072,133120) sume | [133120,135168) idx (512)
    char*  smem_raw = (char*)smem_raw4;
    float* s_emb = (float*)smem_raw;
    float* s_se  = (float*)(smem_raw + 131072);
    int*   s_idx = (int*)  (smem_raw + 133120);
    __shared__ double s_red[TPB];

    const int tid = threadIdx.x;

    // ---- stage codebook into smem (8192 float4) ----
    {
        const float4* e4 = (const float4*)emb;
        float4* s4 = (float4*)s_emb;
#pragma unroll
        for (int i = 0; i < 32; i++) s4[tid + i * 256] = e4[tid + i * 256];
    }
    __syncthreads();

    // ---- per-block ||e_k||^2 (sequential, same order as R3-passing prep) ----
    for (int r = tid; r < K_CODES; r += TPB) {
        const float* row = s_emb + r * D_DIM;
        float s = 0.f;
#pragma unroll
        for (int c = 0; c < D_DIM; c++)
            s = __fadd_rn(s, __fmul_rn(row[c], row[c]));
        s_se[r] = s;
    }
    __syncthreads();

    // ---- load z for 2 pixels, compute ||z||^2 sequentially (ref-order) ----
    const int n0 = blockIdx.x * PIX_PER_BLK + tid;   // pixel ids
    const int n1 = n0 + TPB;
    const size_t zb0 = (size_t)(n0 >> 12) * 262144 + (size_t)((n0 >> 6) & 63) * 64 + (n0 & 63);
    const size_t zb1 = (size_t)(n1 >> 12) * 262144 + (size_t)((n1 >> 6) & 63) * 64 + (n1 & 63);
    const float* zg0 = z + zb0;
    const float* zg1 = z + zb1;

    unsigned long long zp0[32], zp1[32];
    float sumz0 = 0.f, sumz1 = 0.f;
#pragma unroll
    for (int i = 0; i < 32; i++) {
        float a = zg0[(2 * i) * 4096];
        float c = zg0[(2 * i + 1) * 4096];
        sumz0 = __fadd_rn(sumz0, __fmul_rn(a, a));
        sumz0 = __fadd_rn(sumz0, __fmul_rn(c, c));
        zp0[i] = pack2(a, c);
    }
#pragma unroll
    for (int i = 0; i < 32; i++) {
        float a = zg1[(2 * i) * 4096];
        float c = zg1[(2 * i + 1) * 4096];
        sumz1 = __fadd_rn(sumz1, __fmul_rn(a, a));
        sumz1 = __fadd_rn(sumz1, __fmul_rn(c, c));
        zp1[i] = pack2(a, c);
    }

    // ---- argmin over 512 codes for both pixels (FP order identical to R3) ----
    float best0 = 3.4e38f, best1 = 3.4e38f;
    int bidx0 = 0, bidx1 = 0;
    const ulonglong2* s2 = (const ulonglong2*)s_emb;
#pragma unroll 1
    for (int k = 0; k < K_CODES; k++) {
        const ulonglong2* row = s2 + k * 16;
        unsigned long long a00 = 0ULL, a01 = 0ULL;
        unsigned long long a10 = 0ULL, a11 = 0ULL;
#pragma unroll
        for (int i = 0; i < 16; i++) {
            ulonglong2 ev = row[i];
            a00 = fma2(zp0[2 * i],     ev.x, a00);
            a01 = fma2(zp0[2 * i + 1], ev.y, a01);
            a10 = fma2(zp1[2 * i],     ev.x, a10);
            a11 = fma2(zp1[2 * i + 1], ev.y, a11);
        }
        const float se = s_se[k];
        {
            float p0, p1, p2, p3;
            unpack2(a00, p0, p1);
            unpack2(a01, p2, p3);
            float dot  = __fadd_rn(__fadd_rn(p0, p1), __fadd_rn(p2, p3));
            float dist = __fsub_rn(__fadd_rn(sumz0, se), __fmul_rn(2.0f, dot));
            if (dist < best0) { best0 = dist; bidx0 = k; }
        }
        {
            float p0, p1, p2, p3;
            unpack2(a10, p0, p1);
            unpack2(a11, p2, p3);
            float dot  = __fadd_rn(__fadd_rn(p0, p1), __fadd_rn(p2, p3));
            float dist = __fsub_rn(__fadd_rn(sumz1, se), __fmul_rn(2.0f, dot));
            if (dist < best1) { best1 = dist; bidx1 = k; }
        }
    }

    s_idx[tid]       = bidx0;
    s_idx[tid + TPB] = bidx1;

    // ---- quantized_st = fl(z + fl(q - z)), accumulate (q - z)^2 ----
    float lsum0 = 0.f, lsum1 = 0.f;
    {
        float* qout = out + OFF_Q + zb0;
        const float* erow = s_emb + bidx0 * D_DIM;
#pragma unroll
        for (int i = 0; i < 32; i++) {
            float zlo, zhi;
            unpack2(zp0[i], zlo, zhi);
            float d0 = __fsub_rn(erow[2 * i],     zlo);
            float d1 = __fsub_rn(erow[2 * i + 1], zhi);
            lsum0 += d0 * d0 + d1 * d1;
            qout[(2 * i) * 4096]     = __fadd_rn(zlo, d0);
            qout[(2 * i + 1) * 4096] = __fadd_rn(zhi, d1);
        }
    }
    {
        float* qout = out + OFF_Q + zb1;
        const float* erow = s_emb + bidx1 * D_DIM;
#pragma unroll
        for (int i = 0; i < 32; i++) {
            float zlo, zhi;
            unpack2(zp1[i], zlo, zhi);
            float d0 = __fsub_rn(erow[2 * i],     zlo);
            float d1 = __fsub_rn(erow[2 * i + 1], zhi);
            lsum1 += d0 * d0 + d1 * d1;
            qout[(2 * i) * 4096]     = __fadd_rn(zlo, d0);
            qout[(2 * i + 1) * 4096] = __fadd_rn(zhi, d1);
        }
    }

    out[OFF_IDX + (size_t)n0] = (float)bidx0;
    out[OFF_IDX + (size_t)n1] = (float)bidx1;
    atomicAdd(&g_s.counts[bidx0], 1);
    atomicAdd(&g_s.counts[bidx1], 1);

    // ---- block-reduce squared error (double), one atomic per block ----
    s_red[tid] = (double)lsum0 + (double)lsum1;
    __syncthreads();                 // also publishes s_idx
#pragma unroll
    for (int off = 128; off > 0; off >>= 1) {
        if (tid < off) s_red[tid] += s_red[tid + off];
        __syncthreads();
    }
    if (tid == 0) atomicAdd(&g_s.sumsq, s_red[0]);

    // ---- cooperative coalesced one-hot writes (float2: OFF_ENC is 8B-aligned) ----
    const int lane = tid & 31;
    const int warp = tid >> 5;
    const size_t enc_base = OFF_ENC + (size_t)(blockIdx.x * PIX_PER_BLK) * K_CODES;
    for (int r = warp * 64; r < warp * 64 + 64; r++) {
        const int target = s_idx[r];
        float2* rowp = (float2*)(out + enc_base + (size_t)r * K_CODES);
#pragma unroll
        for (int j = lane; j < 256; j += 32) {
            int c0 = j * 2;
            float2 v;
            v.x = (c0     == target) ? 1.f : 0.f;
            v.y = (c0 + 1 == target) ? 1.f : 0.f;
            rowp[j] = v;
        }
    }

    // ---- last block finalizes loss + perplexity ----
    __shared__ int s_last;
    __threadfence();
    __syncthreads();
    if (tid == 0) s_last = (atomicAdd(&g_s.ticket, 1) == NBLK - 1) ? 1 : 0;
    __syncthreads();
    if (s_last) {
        __threadfence();
        double t = 0.0;
        for (int r = tid; r < K_CODES; r += TPB) {
            float pf = (float)g_s.counts[r] * (1.0f / 131072.0f);
            t += (double)(pf * logf(pf + 1e-10f));
        }
        s_red[tid] = t;
        __syncthreads();
#pragma unroll
        for (int off = 128; off > 0; off >>= 1) {
            if (tid < off) s_red[tid] += s_red[tid + off];
            __syncthreads();
        }
        if (tid == 0) {
            out[OFF_PERP] = expf((float)(-s_red[0]));
            double m = g_s.sumsq / 8388608.0;
            float mf = (float)m;
            out[OFF_LOSS] = __fadd_rn(mf, __fmul_rn(0.25f, mf));
        }
    }
}

extern "C" void kernel_launch(void* const* d_in, const int* in_sizes, int n_in,
                              void* d_out, int out_size) {
    const float* z   = (const float*)d_in[0];   // latent_z [32,64,64,64]
    const float* emb = (const float*)d_in[1];   // embedding [512,64]
    float* out = (float*)d_out;

    void* sp = nullptr;
    cudaGetSymbolAddress(&sp, g_s);
    cudaMemsetAsync(sp, 0, sizeof(Scratch), 0);

    const int dyn_smem = 135168;  // 128KB codebook + 2KB norms + 2KB idx
    cudaFuncSetAttribute(vq_fused, cudaFuncAttributeMaxDynamicSharedMemorySize, dyn_smem);
    vq_fused<<<NBLK, TPB, dyn_smem>>>(z, emb, out);
}